// round 2
// baseline (speedup 1.0000x reference)
#include <cuda_runtime.h>
#include <cstdint>

// GlobalFilter: y = irfft(rfft(x, n=10) * W, n=10) == per-dim length-10 circular conv.
// x: [B=8192, DIM=1024, N=10] f32, W: [DIM, 6, 2] f32, y: [B, DIM, 10] f32.

#define DIM        1024
#define NPTS       10
#define ROWS_TILE  512                 // rows per block tile
#define TILE_BYTES (ROWS_TILE * NPTS * 4)   // 20480
#define THREADS    256
#define GRID       740                 // 5 blocks/SM * 148 SMs (even -> tile parity preserved)

// plain layout: g_h[d*10 + j] = h_d[j]
__device__ float g_h[DIM * NPTS];

__device__ __constant__ float COS10[10] = {
    1.0f,  0.80901699437494745f,  0.30901699437494745f, -0.30901699437494745f, -0.80901699437494745f,
   -1.0f, -0.80901699437494745f, -0.30901699437494745f,  0.30901699437494745f,  0.80901699437494745f};
__device__ __constant__ float SIN10[10] = {
    0.0f,  0.58778525229247314f,  0.95105651629515357f,  0.95105651629515357f,  0.58778525229247314f,
    0.0f, -0.58778525229247314f, -0.95105651629515357f, -0.95105651629515357f, -0.58778525229247314f};

__global__ void precompute_h_kernel(const float* __restrict__ w) {
    int d = blockIdx.x * blockDim.x + threadIdx.x;
    if (d >= DIM) return;
    const float4* wp = reinterpret_cast<const float4*>(w + d * 12);
    float4 w0 = wp[0], w1 = wp[1], w2 = wp[2];
    float a[6], b[6];
    a[0] = w0.x; b[0] = w0.y; a[1] = w0.z; b[1] = w0.w;
    a[2] = w1.x; b[2] = w1.y; a[3] = w1.z; b[3] = w1.w;
    a[4] = w2.x; b[4] = w2.y; a[5] = w2.z; b[5] = w2.w;
#pragma unroll
    for (int j = 0; j < NPTS; j++) {
        float acc = a[0] + ((j & 1) ? -a[5] : a[5]);
#pragma unroll
        for (int k = 1; k <= 4; k++) {
            int m = (k * j) % 10;
            acc += 2.0f * (a[k] * COS10[m] - b[k] * SIN10[m]);
        }
        g_h[d * NPTS + j] = 0.1f * acc;
    }
}

// ---- packed f32x2 helpers ----
__device__ __forceinline__ unsigned long long pack2(float lo, float hi) {
    unsigned long long r;
    asm("mov.b64 %0, {%1, %2};" : "=l"(r) : "f"(lo), "f"(hi));
    return r;
}
__device__ __forceinline__ void unpack2(unsigned long long v, float& lo, float& hi) {
    asm("mov.b64 {%0, %1}, %2;" : "=f"(lo), "=f"(hi) : "l"(v));
}
__device__ __forceinline__ unsigned long long fma2(unsigned long long a,
                                                   unsigned long long b,
                                                   unsigned long long c) {
    unsigned long long d;
    asm("fma.rn.f32x2 %0, %1, %2, %3;" : "=l"(d) : "l"(a), "l"(b), "l"(c));
    return d;
}

// SW128 swizzle: XOR byte bits [7:9] into bits [4:6]. Preserves 16B alignment.
__device__ __forceinline__ uint32_t swz(uint32_t b) { return b ^ ((b >> 3) & 0x70u); }

// Compute one row: read x (10 floats at smem byte rb, swizzled), h (same offset in hbuf),
// produce y[10] via packed (m, m+5) circular conv.
__device__ __forceinline__ void conv_row(const char* __restrict__ xbuf,
                                         const char* __restrict__ hbuf,
                                         uint32_t rb, float yout[10]) {
    float xr[10], hr[10];
#pragma unroll
    for (int j = 0; j < 5; j++) {
        float2 t = *reinterpret_cast<const float2*>(xbuf + swz(rb + 8 * j));
        xr[2 * j] = t.x; xr[2 * j + 1] = t.y;
        float2 u = *reinterpret_cast<const float2*>(hbuf + swz(rb + 8 * j));
        hr[2 * j] = u.x; hr[2 * j + 1] = u.y;
    }
    unsigned long long hp[10];
#pragma unroll
    for (int i = 0; i < 10; i++) hp[i] = pack2(hr[i], hr[(i + 5) % 10]);
    unsigned long long acc[5];
#pragma unroll
    for (int m = 0; m < 5; m++) acc[m] = 0ULL;
#pragma unroll
    for (int j = 0; j < 10; j++) {
        unsigned long long xb = pack2(xr[j], xr[j]);
#pragma unroll
        for (int m = 0; m < 5; m++) {
            acc[m] = fma2(hp[(m - j + 10) % 10], xb, acc[m]);
        }
    }
#pragma unroll
    for (int m = 0; m < 5; m++) unpack2(acc[m], yout[m], yout[m + 5]);
}

__global__ void __launch_bounds__(THREADS, 5)
global_filter_kernel(const float* __restrict__ x, float* __restrict__ y, int ntiles) {
    __shared__ float4 sbuf[2 * TILE_BYTES / 16];   // 40960 B: [xbuf | hbuf]
    char* xbuf = reinterpret_cast<char*>(sbuf);
    char* hbuf = xbuf + TILE_BYTES;

    int tid = threadIdx.x;

    // Stage this block's h half once (tile parity -> dim half, preserved since GRID is even).
    int dimHalf = blockIdx.x & 1;
    {
        const float4* hs = reinterpret_cast<const float4*>(g_h + dimHalf * (DIM / 2) * NPTS);
#pragma unroll
        for (int k = 0; k < 5; k++) {
            float4 v = hs[k * THREADS + tid];
            *reinterpret_cast<float4*>(hbuf + swz((uint32_t)(k * THREADS + tid) * 16u)) = v;
        }
    }

    for (int tile = blockIdx.x; tile < ntiles; tile += gridDim.x) {
        // Front-batch coalesced loads (regs only) before the barrier.
        const float4* xs = reinterpret_cast<const float4*>(x) + (size_t)tile * (TILE_BYTES / 16);
        float4 v0 = xs[0 * THREADS + tid];
        float4 v1 = xs[1 * THREADS + tid];
        float4 v2 = xs[2 * THREADS + tid];
        float4 v3 = xs[3 * THREADS + tid];
        float4 v4 = xs[4 * THREADS + tid];

        __syncthreads();  // previous tile's compute reads done -> safe to overwrite xbuf
        *reinterpret_cast<float4*>(xbuf + swz((uint32_t)(0 * THREADS + tid) * 16u)) = v0;
        *reinterpret_cast<float4*>(xbuf + swz((uint32_t)(1 * THREADS + tid) * 16u)) = v1;
        *reinterpret_cast<float4*>(xbuf + swz((uint32_t)(2 * THREADS + tid) * 16u)) = v2;
        *reinterpret_cast<float4*>(xbuf + swz((uint32_t)(3 * THREADS + tid) * 16u)) = v3;
        *reinterpret_cast<float4*>(xbuf + swz((uint32_t)(4 * THREADS + tid) * 16u)) = v4;
        __syncthreads();

        // Thread owns local rows 2*tid, 2*tid+1 (bytes 80*tid, 80*tid+40 in both buffers).
        float* yo = y + ((size_t)tile * ROWS_TILE + 2u * tid) * NPTS;  // 16B aligned
        float ya[10];

        conv_row(xbuf, hbuf, 80u * tid, ya);
        *reinterpret_cast<float4*>(yo + 0) = make_float4(ya[0], ya[1], ya[2], ya[3]);
        *reinterpret_cast<float4*>(yo + 4) = make_float4(ya[4], ya[5], ya[6], ya[7]);
        *reinterpret_cast<float2*>(yo + 8) = make_float2(ya[8], ya[9]);

        conv_row(xbuf, hbuf, 80u * tid + 40u, ya);
        *reinterpret_cast<float2*>(yo + 10) = make_float2(ya[0], ya[1]);
        *reinterpret_cast<float4*>(yo + 12) = make_float4(ya[2], ya[3], ya[4], ya[5]);
        *reinterpret_cast<float4*>(yo + 16) = make_float4(ya[6], ya[7], ya[8], ya[9]);
    }
}

extern "C" void kernel_launch(void* const* d_in, const int* in_sizes, int n_in,
                              void* d_out, int out_size) {
    const float* x = (const float*)d_in[0];
    const float* w = (const float*)d_in[1];
    float* y = (float*)d_out;

    precompute_h_kernel<<<(DIM + 255) / 256, 256>>>(w);

    int nrows  = in_sizes[0] / NPTS;          // 8192*1024
    int ntiles = nrows / ROWS_TILE;           // 16384
    global_filter_kernel<<<GRID, THREADS>>>(x, y, ntiles);
}

// round 3
// speedup vs baseline: 1.5961x; 1.5961x over previous
#include <cuda_runtime.h>
#include <cstdint>

// GlobalFilter: y = irfft(rfft(x, n=10) * W, n=10) == per-dim length-10 circular conv.
// x: [B=8192, DIM=1024, N=10] f32, W: [DIM, 6, 2] f32, y: [B, DIM, 10] f32.

#define DIM            1024
#define NPTS           10
#define THREADS        256
#define ROWS_PER_BLOCK 512                       // 2 rows per thread
#define F4_PER_BLOCK   (ROWS_PER_BLOCK * NPTS / 4)   // 1280 float4 per block
#define F4_PER_WARP    160
#define SMEM_BYTES     (THREADS * 80)            // 20480 B (2560 B per warp)

// Transposed, pair-packed filter: g_hvT[j*512 + p] = (h[2p][j], h[2p+1][j]) as 2 floats.
__device__ unsigned long long g_hvT[NPTS * (DIM / 2)];

__device__ __constant__ float COS10[10] = {
    1.0f,  0.80901699437494745f,  0.30901699437494745f, -0.30901699437494745f, -0.80901699437494745f,
   -1.0f, -0.80901699437494745f, -0.30901699437494745f,  0.30901699437494745f,  0.80901699437494745f};
__device__ __constant__ float SIN10[10] = {
    0.0f,  0.58778525229247314f,  0.95105651629515357f,  0.95105651629515357f,  0.58778525229247314f,
    0.0f, -0.58778525229247314f, -0.95105651629515357f, -0.95105651629515357f, -0.58778525229247314f};

__global__ void precompute_h_kernel(const float* __restrict__ w) {
    int d = blockIdx.x * blockDim.x + threadIdx.x;
    if (d >= DIM) return;
    const float4* wp = reinterpret_cast<const float4*>(w + d * 12);
    float4 w0 = wp[0], w1 = wp[1], w2 = wp[2];
    float a[6], b[6];
    a[0] = w0.x; b[0] = w0.y; a[1] = w0.z; b[1] = w0.w;
    a[2] = w1.x; b[2] = w1.y; a[3] = w1.z; b[3] = w1.w;
    a[4] = w2.x; b[4] = w2.y; a[5] = w2.z; b[5] = w2.w;

    float* hf = reinterpret_cast<float*>(g_hvT);
#pragma unroll
    for (int j = 0; j < NPTS; j++) {
        float acc = a[0] + ((j & 1) ? -a[5] : a[5]);
#pragma unroll
        for (int k = 1; k <= 4; k++) {
            int m = (k * j) % 10;
            acc += 2.0f * (a[k] * COS10[m] - b[k] * SIN10[m]);
        }
        // u64 slot (j, p=d/2); lo half for even d, hi half for odd d
        hf[(j * (DIM / 2) + (d >> 1)) * 2 + (d & 1)] = 0.1f * acc;
    }
}

// ---- packed f32x2 helpers ----
__device__ __forceinline__ unsigned long long pack2(float lo, float hi) {
    unsigned long long r;
    asm("mov.b64 %0, {%1, %2};" : "=l"(r) : "f"(lo), "f"(hi));
    return r;
}
__device__ __forceinline__ unsigned long long fma2(unsigned long long a,
                                                   unsigned long long b,
                                                   unsigned long long c) {
    unsigned long long d;
    asm("fma.rn.f32x2 %0, %1, %2, %3;" : "=l"(d) : "l"(a), "l"(b), "l"(c));
    return d;
}
__device__ __forceinline__ void unpack2(unsigned long long v, float& lo, float& hi) {
    asm("mov.b64 {%0, %1}, %2;" : "=f"(lo), "=f"(hi) : "l"(v));
}

__device__ __forceinline__ uint32_t smem_u32(const void* p) {
    return (uint32_t)__cvta_generic_to_shared(p);
}

__global__ void __launch_bounds__(THREADS)
global_filter_kernel(const float* __restrict__ x, float* __restrict__ y) {
    __shared__ __align__(16) char smem[SMEM_BYTES];

    int tid = threadIdx.x;
    int w   = tid >> 5;      // warp in block
    int t   = tid & 31;      // lane

    size_t f4base = (size_t)blockIdx.x * F4_PER_BLOCK + (size_t)w * F4_PER_WARP;
    const float4* xg = reinterpret_cast<const float4*>(x) + f4base;
    char* sw = smem + w * 2560;     // this warp's staging tile

    // Phase 1: coalesced global -> smem via cp.async (L1 bypass; x is streaming)
#pragma unroll
    for (int k = 0; k < 5; k++) {
        uint32_t sa = smem_u32(sw + (t + 32 * k) * 16);
        const float4* ga = xg + t + 32 * k;
        asm volatile("cp.async.cg.shared.global [%0], [%1], 16;\n" :: "r"(sa), "l"(ga));
    }
    asm volatile("cp.async.commit_group;\n");

    // Overlap: load packed filter pairs (coalesced, L1/L2 resident, 40KB total)
    int p = (blockIdx.x * 256 + w * 32 + t) & (DIM / 2 - 1);  // no intra-warp wrap
    unsigned long long hv[10];
#pragma unroll
    for (int j = 0; j < 10; j++) hv[j] = __ldg(&g_hvT[j * (DIM / 2) + p]);

    asm volatile("cp.async.wait_group 0;\n");
    __syncwarp();

    // Phase 2: each thread reads its OWN 80B (rows 2t, 2t+1 of this warp's tile).
    // LDS.128 at 80*t + 16*i: 16B aligned, conflict-free (20t mod 32 covers all banks).
    const float4* sx = reinterpret_cast<const float4*>(sw + 80 * t);
    float4 r0 = sx[0], r1 = sx[1], r2 = sx[2], r3 = sx[3], r4 = sx[4];
    float xr[20] = {r0.x, r0.y, r0.z, r0.w, r1.x, r1.y, r1.z, r1.w, r2.x, r2.y,
                    r2.z, r2.w, r3.x, r3.y, r3.z, r3.w, r4.x, r4.y, r4.z, r4.w};

    unsigned long long xv[10];
#pragma unroll
    for (int j = 0; j < 10; j++) xv[j] = pack2(xr[j], xr[10 + j]);

    unsigned long long acc[10];
#pragma unroll
    for (int n = 0; n < 10; n++) acc[n] = 0ULL;
#pragma unroll
    for (int j = 0; j < 10; j++) {
#pragma unroll
        for (int n = 0; n < 10; n++) {
            acc[n] = fma2(hv[(n - j + 10) % 10], xv[j], acc[n]);
        }
    }

    // Phase 3: write y into OWN 80B region (no cross-thread hazard with phase 2),
    // then warp-coalesced copy out.
    float y0[10], y1[10];
#pragma unroll
    for (int n = 0; n < 10; n++) unpack2(acc[n], y0[n], y1[n]);

    float4* sy = reinterpret_cast<float4*>(sw + 80 * t);
    sy[0] = make_float4(y0[0], y0[1], y0[2], y0[3]);
    sy[1] = make_float4(y0[4], y0[5], y0[6], y0[7]);
    sy[2] = make_float4(y0[8], y0[9], y1[0], y1[1]);
    sy[3] = make_float4(y1[2], y1[3], y1[4], y1[5]);
    sy[4] = make_float4(y1[6], y1[7], y1[8], y1[9]);
    __syncwarp();

    float4* yg = reinterpret_cast<float4*>(y) + f4base;
    const float4* sr = reinterpret_cast<const float4*>(sw);
#pragma unroll
    for (int k = 0; k < 5; k++) {
        __stcs(yg + t + 32 * k, sr[t + 32 * k]);
    }
}

extern "C" void kernel_launch(void* const* d_in, const int* in_sizes, int n_in,
                              void* d_out, int out_size) {
    const float* x = (const float*)d_in[0];
    const float* w = (const float*)d_in[1];
    float* y = (float*)d_out;

    precompute_h_kernel<<<(DIM + 255) / 256, 256>>>(w);

    int nrows  = in_sizes[0] / NPTS;            // 8192*1024 = 8,388,608
    int blocks = nrows / ROWS_PER_BLOCK;        // 16384
    global_filter_kernel<<<blocks, THREADS>>>(x, y);
}